// round 12
// baseline (speedup 1.0000x reference)
#include <cuda_runtime.h>
#include <cuda_bf16.h>
#include <math.h>
#include <stdint.h>

// Problem shape (fixed by reference setup_inputs)
#define B_ROWS 2048
#define E_CODES 512
#define DIM     16384

// Output layout: tuple (loss, quantized_st, perplexity, encodings) flattened
#define OFF_LOSS 0ULL
#define OFF_Q    1ULL
#define OFF_PERP (1ULL + (unsigned long long)B_ROWS * DIM)
#define OFF_ENC  (OFF_PERP + 1ULL)

#define KSPLIT 4
#define TH 16.0f          // refine margin: ~40 sigma of bf16 score error
#define MAXCAND 32768

// ---------------------------------------------------------------------------
// Scratch (device globals: no allocations allowed)
__device__ __align__(16) __nv_bfloat16 g_Ah[(size_t)B_ROWS * DIM];
__device__ __align__(16) __nv_bfloat16 g_Bh[(size_t)E_CODES * DIM];
__device__ __align__(16) float         g_Dpart[(size_t)KSPLIT * B_ROWS * E_CODES]; // 16 MB
__device__ float               g_cb_norm[E_CODES];
__device__ unsigned long long  g_keys[B_ROWS];     // (sortable_score<<32)|idx
__device__ uint32_t            g_cand[MAXCAND];
__device__ int                 g_ncand;
__device__ int                 g_counts[E_CODES];
__device__ double              g_xnorm;

// ---------------------------------------------------------------------------
__device__ __forceinline__ uint32_t smem_u32(const void* p) {
    uint32_t a;
    asm("{ .reg .u64 t; cvta.to.shared.u64 t, %1; cvt.u32.u64 %0, t; }" : "=r"(a) : "l"(p));
    return a;
}
#define CP_ASYNC16(dst, src) \
    asm volatile("cp.async.cg.shared.global [%0], [%1], 16;" :: "r"(dst), "l"(src) : "memory")
#define CP_COMMIT() asm volatile("cp.async.commit_group;" ::: "memory")
#define CP_WAIT1()  asm volatile("cp.async.wait_group 1;" ::: "memory")

#define LDSM_X4(r, addr)                                                        \
    asm volatile("ldmatrix.sync.aligned.m8n8.x4.shared.b16 {%0,%1,%2,%3}, [%4];" \
        : "=r"((r)[0]), "=r"((r)[1]), "=r"((r)[2]), "=r"((r)[3]) : "r"(addr))

#define MMA_BF16(d, a0, a1, a2, a3, b0, b1)                                     \
    asm volatile("mma.sync.aligned.m16n8k16.row.col.f32.bf16.bf16.f32 "         \
        "{%0,%1,%2,%3}, {%4,%5,%6,%7}, {%8,%9}, {%0,%1,%2,%3};"                 \
        : "+f"((d)[0]), "+f"((d)[1]), "+f"((d)[2]), "+f"((d)[3])                \
        : "r"(a0), "r"(a1), "r"(a2), "r"(a3), "r"(b0), "r"(b1))

// SW128 swizzle (128-byte rows)
__device__ __forceinline__ uint32_t swz(uint32_t off) { return off ^ ((off >> 3) & 0x70); }

// sortable-float encode/decode (ascending order == float order)
__device__ __forceinline__ unsigned f2sort(float f) {
    unsigned u = __float_as_uint(f);
    return (u & 0x80000000u) ? ~u : (u | 0x80000000u);
}
__device__ __forceinline__ float sort2f(unsigned u) {
    return __uint_as_float((u & 0x80000000u) ? (u & 0x7fffffffu) : ~u);
}
__device__ __forceinline__ unsigned pack_bf2(float x, float y) {
    __nv_bfloat162 h = __halves2bfloat162(__float2bfloat16(x), __float2bfloat16(y));
    return *(unsigned*)&h;
}

// ---------------------------------------------------------------------------
__global__ void k_init() {
    int t = blockIdx.x * blockDim.x + threadIdx.x;
    if (t < E_CODES) g_counts[t] = 0;
    if (t == 0) { g_xnorm = 0.0; g_ncand = 0; }
}

// ---------------------------------------------------------------------------
__device__ __forceinline__ float block_reduce_sum(float v) {
    __shared__ float red[32];
    int lane = threadIdx.x & 31;
    int w    = threadIdx.x >> 5;
    #pragma unroll
    for (int o = 16; o > 0; o >>= 1) v += __shfl_down_sync(0xffffffffu, v, o);
    if (lane == 0) red[w] = v;
    __syncthreads();
    if (w == 0) {
        v = (lane < ((int)blockDim.x >> 5)) ? red[lane] : 0.0f;
        #pragma unroll
        for (int o = 16; o > 0; o >>= 1) v += __shfl_down_sync(0xffffffffu, v, o);
    }
    return v;
}

// ---------------------------------------------------------------------------
// fp32 -> bf16 for inputs and codebook (8 floats/thread, 16B stores);
// accumulate sum(x^2) over inputs.
__global__ void k_convert(const float* __restrict__ A, const float* __restrict__ Cb) {
    const size_t nA8 = (size_t)B_ROWS * DIM / 8;
    const size_t nB8 = (size_t)E_CODES * DIM / 8;
    const size_t gid = blockIdx.x * (size_t)blockDim.x + threadIdx.x;
    const size_t stride = (size_t)gridDim.x * blockDim.x;
    float xs = 0.0f;
    for (size_t j = gid; j < nA8; j += stride) {
        const float4* pa = (const float4*)A + 2 * j;
        float4 v0 = pa[0], v1 = pa[1];
        uint4 hp;
        hp.x = pack_bf2(v0.x, v0.y); hp.y = pack_bf2(v0.z, v0.w);
        hp.z = pack_bf2(v1.x, v1.y); hp.w = pack_bf2(v1.z, v1.w);
        *(uint4*)(g_Ah + 8 * j) = hp;
        xs += v0.x * v0.x + v0.y * v0.y + v0.z * v0.z + v0.w * v0.w
            + v1.x * v1.x + v1.y * v1.y + v1.z * v1.z + v1.w * v1.w;
    }
    for (size_t j = gid; j < nB8; j += stride) {
        const float4* pb = (const float4*)Cb + 2 * j;
        float4 v0 = pb[0], v1 = pb[1];
        uint4 hp;
        hp.x = pack_bf2(v0.x, v0.y); hp.y = pack_bf2(v0.z, v0.w);
        hp.z = pack_bf2(v1.x, v1.y); hp.w = pack_bf2(v1.z, v1.w);
        *(uint4*)(g_Bh + 8 * j) = hp;
    }
    float tot = block_reduce_sum(xs);
    if (threadIdx.x == 0) atomicAdd(&g_xnorm, (double)tot);
}

// ---------------------------------------------------------------------------
// ||e||^2 per codebook row (fp32, from original codebook; deterministic tree)
__global__ void k_cbnorm(const float* __restrict__ cb) {
    int e = blockIdx.x;
    const float4* row = (const float4*)(cb + (size_t)e * DIM);
    float s = 0.0f;
    for (int j = threadIdx.x; j < DIM / 4; j += blockDim.x) {
        float4 v = row[j];
        s += v.x * v.x + v.y * v.y + v.z * v.z + v.w * v.w;
    }
    float tot = block_reduce_sum(s);
    if (threadIdx.x == 0) g_cb_norm[e] = tot;
}

// ---------------------------------------------------------------------------
// bf16 GEMM via mma.sync (HMMA): dot(x_b, e_n) fp32 accum, single product.
// CTA tile 128x128, 8 warps (warp tile 32x64), KC=64, 3-stage cp.async.
// Loader addressing hoisted: per thread, 2 running src pointers + constant
// dst offsets (32-row stride preserves swizzle bits, so dst is uniform-inc).
#define MT      128
#define NT      128
#define KC      64
#define NSTAGE  3
#define KSLICE  (DIM / KSPLIT)               // 4096
#define ITERS   (KSLICE / KC)                // 64
#define TILE_B  (128 * 128)                  // 16 KB
#define STAGE_B (2 * TILE_B)                 // 32 KB
#define SMEM_TOTAL (NSTAGE * STAGE_B)        // 98304 B

__global__ void __launch_bounds__(256, 2) k_mma() {
    extern __shared__ __align__(128) char smem[];
    const uint32_t sb = smem_u32(smem);
    const int tid  = threadIdx.x;
    const int wid  = tid >> 5;
    const int lane = tid & 31;
    const int wm   = wid & 3;                // m block (32 rows)
    const int wn   = wid >> 2;               // n block (64 cols)
    const int m0   = blockIdx.x * MT;
    const int n0   = blockIdx.y * NT;
    const int kz   = blockIdx.z * KSLICE;

    // loader thread geometry: row r0 = tid>>3 (0..31, +32*jj), chunk c = tid&7
    const int r0 = tid >> 3;
    const int c  = tid & 7;
    const __nv_bfloat16* srcA = g_Ah + (size_t)(m0 + r0) * DIM + kz + c * 8;
    const __nv_bfloat16* srcB = g_Bh + (size_t)(n0 + r0) * DIM + kz + c * 8;
    const uint32_t dst0 = sb + swz((uint32_t)(r0 * 128 + c * 16));

    float acc[2][8][4];
    #pragma unroll
    for (int mi = 0; mi < 2; mi++)
        #pragma unroll
        for (int nj = 0; nj < 8; nj++)
            #pragma unroll
            for (int q = 0; q < 4; q++) acc[mi][nj][q] = 0.0f;

    // prologue: stages 0,1
    #pragma unroll
    for (int p = 0; p < NSTAGE - 1; p++) {
        uint32_t d = dst0 + p * STAGE_B;
        #pragma unroll
        for (int jj = 0; jj < 4; jj++) {
            CP_ASYNC16(d + jj * 4096,          srcA + (size_t)jj * 32 * DIM);
            CP_ASYNC16(d + TILE_B + jj * 4096, srcB + (size_t)jj * 32 * DIM);
        }
        CP_COMMIT();
        srcA += KC; srcB += KC;
    }

    const uint32_t lrow = (lane & 15);
    const uint32_t lcol = (lane >> 4) * 16;

    int st_load = NSTAGE - 1;                 // stage to fill next
    for (int i = 0; i < ITERS; i++) {
        const int st = i % NSTAGE;
        CP_WAIT1();
        __syncthreads();
        if (i + NSTAGE - 1 < ITERS) {
            uint32_t d = dst0 + st_load * STAGE_B;
            #pragma unroll
            for (int jj = 0; jj < 4; jj++) {
                CP_ASYNC16(d + jj * 4096,          srcA + (size_t)jj * 32 * DIM);
                CP_ASYNC16(d + TILE_B + jj * 4096, srcB + (size_t)jj * 32 * DIM);
            }
            srcA += KC; srcB += KC;
            if (++st_load == NSTAGE) st_load = 0;
        }
        CP_COMMIT();

        const uint32_t s0 = sb + st * STAGE_B;
        #pragma unroll
        for (int ks = 0; ks < 4; ks++) {
            const uint32_t ko = ks * 32 + lcol;
            uint32_t a[2][4], b[4][4];
            #pragma unroll
            for (int mi = 0; mi < 2; mi++) {
                uint32_t ro = (wm * 32 + mi * 16 + lrow) * 128;
                LDSM_X4(a[mi], s0 + swz(ro + ko));
            }
            #pragma unroll
            for (int nq = 0; nq < 4; nq++) {
                uint32_t ro = (wn * 64 + nq * 16 + lrow) * 128;
                LDSM_X4(b[nq], s0 + TILE_B + swz(ro + ko));
            }
            #pragma unroll
            for (int nq = 0; nq < 4; nq++)
                #pragma unroll
                for (int mi = 0; mi < 2; mi++) {
                    MMA_BF16(acc[mi][2 * nq],     a[mi][0], a[mi][1], a[mi][2], a[mi][3],
                             b[nq][0], b[nq][2]);
                    MMA_BF16(acc[mi][2 * nq + 1], a[mi][0], a[mi][1], a[mi][2], a[mi][3],
                             b[nq][1], b[nq][3]);
                }
        }
    }

    // epilogue: write partial dots
    #pragma unroll
    for (int mi = 0; mi < 2; mi++) {
        #pragma unroll
        for (int nj = 0; nj < 8; nj++) {
            int row = m0 + wm * 32 + mi * 16 + (lane >> 2);
            int col = n0 + wn * 64 + nj * 8 + (lane & 3) * 2;
            float* d = &g_Dpart[((size_t)blockIdx.z * B_ROWS + row) * E_CODES + col];
            *(float2*)d = make_float2(acc[mi][nj][0], acc[mi][nj][1]);
            *(float2*)(d + 8 * E_CODES) = make_float2(acc[mi][nj][2], acc[mi][nj][3]);
        }
    }
}

// ---------------------------------------------------------------------------
// bf16 argmin per row + near-tie candidate extraction (one warp per row).
// float4 loads over Dpart; writes sentinel itself when refinement is needed.
__global__ void k_argmin() {
    const int row  = blockIdx.x * 8 + (threadIdx.x >> 5);
    const int lane = threadIdx.x & 31;
    const size_t SL = (size_t)B_ROWS * E_CODES;
    const float4* d4 = (const float4*)&g_Dpart[(size_t)row * E_CODES];
    float s[16];
    float m = 3.4e38f;
    #pragma unroll
    for (int j = 0; j < 4; j++) {
        int v4 = j * 32 + lane;                    // float4 index within row
        float4 dot = d4[v4];
        #pragma unroll
        for (int z = 1; z < KSPLIT; z++) {
            float4 t = d4[z * (SL / 4) + v4];
            dot.x += t.x; dot.y += t.y; dot.z += t.z; dot.w += t.w;
        }
        int e = v4 * 4;
        s[4 * j + 0] = g_cb_norm[e + 0] - 2.0f * dot.x;
        s[4 * j + 1] = g_cb_norm[e + 1] - 2.0f * dot.y;
        s[4 * j + 2] = g_cb_norm[e + 2] - 2.0f * dot.z;
        s[4 * j + 3] = g_cb_norm[e + 3] - 2.0f * dot.w;
        m = fminf(fminf(fminf(m, s[4 * j]), s[4 * j + 1]),
                  fminf(s[4 * j + 2], s[4 * j + 3]));
    }
    #pragma unroll
    for (int o = 16; o > 0; o >>= 1) m = fminf(m, __shfl_xor_sync(0xffffffffu, m, o));

    int cnt = 0;
    #pragma unroll
    for (int j = 0; j < 16; j++) cnt += (s[j] <= m + TH);
    #pragma unroll
    for (int o = 16; o > 0; o >>= 1) cnt += __shfl_xor_sync(0xffffffffu, cnt, o);

    if (cnt == 1) {
        int be = 0x7fffffff;
        #pragma unroll
        for (int j = 0; j < 16; j++)
            if (s[j] <= m + TH) be = (j >> 2) * 128 + lane * 4 + (j & 3);
        #pragma unroll
        for (int o = 16; o > 0; o >>= 1) be = min(be, __shfl_xor_sync(0xffffffffu, be, o));
        if (lane == 0)
            g_keys[row] = ((unsigned long long)f2sort(m) << 32) | (unsigned)be;
    } else {
        if (lane == 0) g_keys[row] = 0xFFFFFFFFFFFFFFFFULL;
        #pragma unroll
        for (int j = 0; j < 16; j++) {
            if (s[j] <= m + TH) {
                int e = (j >> 2) * 128 + lane * 4 + (j & 3);
                int slot = atomicAdd(&g_ncand, 1);
                if (slot < MAXCAND) g_cand[slot] = ((unsigned)row << 9) | (unsigned)e;
            }
        }
    }
}

// ---------------------------------------------------------------------------
// exact fp32 re-score of near-tie candidates; atomicMin sortable keys
__global__ void k_refine(const float* __restrict__ A, const float* __restrict__ Cb) {
    const int n = g_ncand;
    for (int j = blockIdx.x; j < n && j < MAXCAND; j += gridDim.x) {
        uint32_t cd  = g_cand[j];
        int row  = cd >> 9;
        int code = cd & 511;
        const float4* x = (const float4*)(A  + (size_t)row  * DIM);
        const float4* e = (const float4*)(Cb + (size_t)code * DIM);
        float dot = 0.0f;
        for (int i = threadIdx.x; i < DIM / 4; i += blockDim.x) {
            float4 xv = x[i], ev = e[i];
            dot += xv.x * ev.x + xv.y * ev.y + xv.z * ev.z + xv.w * ev.w;
        }
        float tot = block_reduce_sum(dot);
        if (threadIdx.x == 0) {
            float sc = g_cb_norm[code] - 2.0f * tot;
            unsigned long long key = ((unsigned long long)f2sort(sc) << 32) | (unsigned)code;
            atomicMin(&g_keys[row], key);
        }
        __syncthreads();
    }
}

// ---------------------------------------------------------------------------
// per row b: one-hot enc row + histogram + gather codebook row (vectorized).
__global__ void k_gather(const float* __restrict__ Cb, float* __restrict__ out) {
    int b   = blockIdx.x;
    int idx = (int)(g_keys[b] & 0xFFFFFFFFu);

    float2* enc = (float2*)(out + OFF_ENC + (size_t)b * E_CODES);
    if (threadIdx.x < 256) enc[threadIdx.x] = make_float2(0.f, 0.f);
    __syncthreads();
    if (threadIdx.x == 0) {
        out[OFF_ENC + (size_t)b * E_CODES + idx] = 1.0f;
        atomicAdd(&g_counts[idx], 1);
    }

    const float*  q  = Cb + (size_t)idx * DIM;
    const float4* q4 = (const float4*)q;
    float* o = out + OFF_Q + (size_t)b * DIM;
    if (threadIdx.x < 3) o[threadIdx.x] = q[threadIdx.x];        // prefix 0..2
    if (threadIdx.x == 3) o[DIM - 1] = q[DIM - 1];               // tail 16383
    float4* o4 = (float4*)(o + 3);                               // 16B aligned
    for (int t = threadIdx.x; t < (DIM - 4) / 4; t += blockDim.x) {
        float4 s0 = q4[t];
        float4 s1 = q4[t + 1];
        o4[t] = make_float4(s0.w, s1.x, s1.y, s1.z);
    }
}

// ---------------------------------------------------------------------------
// loss from Sum(best scores) + Sum(x^2); perplexity from counts
__global__ void k_finalize(float* __restrict__ out) {
    __shared__ double sh[512];
    int t = threadIdx.x;

    double s = 0.0;
    for (int r = t; r < B_ROWS; r += 512)
        s += (double)sort2f((unsigned)(g_keys[r] >> 32));
    sh[t] = s;
    __syncthreads();
    for (int k = 256; k > 0; k >>= 1) {
        if (t < k) sh[t] += sh[t + k];
        __syncthreads();
    }
    double score_sum = sh[0];
    __syncthreads();

    float p = (float)g_counts[t] / (float)B_ROWS;
    sh[t] = (double)(p * logf(p + 1e-10f));
    __syncthreads();
    for (int k = 256; k > 0; k >>= 1) {
        if (t < k) sh[t] += sh[t + k];
        __syncthreads();
    }
    if (t == 0) {
        out[OFF_PERP] = expf(-(float)sh[0]);
        double mse = (score_sum + g_xnorm) / ((double)B_ROWS * (double)DIM);
        out[OFF_LOSS] = (float)(1.25 * mse);
    }
}

// ---------------------------------------------------------------------------
extern "C" void kernel_launch(void* const* d_in, const int* in_sizes, int n_in,
                              void* d_out, int out_size) {
    const float* inputs   = (const float*)d_in[0];   // [2048, 16384]
    const float* codebook = (const float*)d_in[1];   // [512, 16384]
    float* out = (float*)d_out;
    (void)in_sizes; (void)n_in; (void)out_size;

    static int smem_set = 0;
    if (!smem_set) {
        cudaFuncSetAttribute(k_mma, cudaFuncAttributeMaxDynamicSharedMemorySize, SMEM_TOTAL);
        smem_set = 1;
    }

    k_init<<<2, 256>>>();
    k_convert<<<2048, 256>>>(inputs, codebook);
    k_cbnorm<<<E_CODES, 256>>>(codebook);

    dim3 grid(B_ROWS / MT, E_CODES / NT, KSPLIT);    // (16, 4, 4) = 256 CTAs
    k_mma<<<grid, 256, SMEM_TOTAL>>>();

    k_argmin<<<B_ROWS / 8, 256>>>();
    k_refine<<<1024, 256>>>(inputs, codebook);
    k_gather<<<B_ROWS, 256>>>(codebook, out);
    k_finalize<<<1, 512>>>(out);
}

// round 13
// speedup vs baseline: 1.0005x; 1.0005x over previous
#include <cuda_runtime.h>
#include <cuda_bf16.h>
#include <math.h>
#include <stdint.h>

// Problem shape (fixed by reference setup_inputs)
#define B_ROWS 2048
#define E_CODES 512
#define DIM     16384

// Output layout: tuple (loss, quantized_st, perplexity, encodings) flattened
#define OFF_LOSS 0ULL
#define OFF_Q    1ULL
#define OFF_PERP (1ULL + (unsigned long long)B_ROWS * DIM)
#define OFF_ENC  (OFF_PERP + 1ULL)

#define KSPLIT 4
#define TH 16.0f          // refine margin: ~40 sigma of bf16 score error
#define MAXCAND 32768

// ---------------------------------------------------------------------------
// Scratch (device globals: no allocations allowed)
__device__ __align__(16) __nv_bfloat16 g_Ah[(size_t)B_ROWS * DIM];
__device__ __align__(16) __nv_bfloat16 g_Bh[(size_t)E_CODES * DIM];
__device__ __align__(16) float         g_Dpart[(size_t)KSPLIT * B_ROWS * E_CODES]; // 16 MB
__device__ float               g_cb_norm[E_CODES];
__device__ unsigned long long  g_keys[B_ROWS];     // (sortable_score<<32)|idx
__device__ uint32_t            g_cand[MAXCAND];
__device__ int                 g_ncand;
__device__ int                 g_counts[E_CODES];
__device__ double              g_xnorm;

// ---------------------------------------------------------------------------
__device__ __forceinline__ uint32_t smem_u32(const void* p) {
    uint32_t a;
    asm("{ .reg .u64 t; cvta.to.shared.u64 t, %1; cvt.u32.u64 %0, t; }" : "=r"(a) : "l"(p));
    return a;
}
#define CP_ASYNC16(dst, src) \
    asm volatile("cp.async.cg.shared.global [%0], [%1], 16;" :: "r"(dst), "l"(src) : "memory")
#define CP_COMMIT() asm volatile("cp.async.commit_group;" ::: "memory")
#define CP_WAIT1()  asm volatile("cp.async.wait_group 1;" ::: "memory")

#define LDSM_X4(r, addr)                                                        \
    asm volatile("ldmatrix.sync.aligned.m8n8.x4.shared.b16 {%0,%1,%2,%3}, [%4];" \
        : "=r"((r)[0]), "=r"((r)[1]), "=r"((r)[2]), "=r"((r)[3]) : "r"(addr))

#define MMA_BF16(d, a0, a1, a2, a3, b0, b1)                                     \
    asm volatile("mma.sync.aligned.m16n8k16.row.col.f32.bf16.bf16.f32 "         \
        "{%0,%1,%2,%3}, {%4,%5,%6,%7}, {%8,%9}, {%0,%1,%2,%3};"                 \
        : "+f"((d)[0]), "+f"((d)[1]), "+f"((d)[2]), "+f"((d)[3])                \
        : "r"(a0), "r"(a1), "r"(a2), "r"(a3), "r"(b0), "r"(b1))

// SW128 swizzle (128-byte rows)
__device__ __forceinline__ uint32_t swz(uint32_t off) { return off ^ ((off >> 3) & 0x70); }

// sortable-float encode/decode (ascending order == float order)
__device__ __forceinline__ unsigned f2sort(float f) {
    unsigned u = __float_as_uint(f);
    return (u & 0x80000000u) ? ~u : (u | 0x80000000u);
}
__device__ __forceinline__ float sort2f(unsigned u) {
    return __uint_as_float((u & 0x80000000u) ? (u & 0x7fffffffu) : ~u);
}
__device__ __forceinline__ unsigned pack_bf2(float x, float y) {
    __nv_bfloat162 h = __halves2bfloat162(__float2bfloat16(x), __float2bfloat16(y));
    return *(unsigned*)&h;
}

// ---------------------------------------------------------------------------
__global__ void k_init() {
    int t = blockIdx.x * blockDim.x + threadIdx.x;
    if (t < E_CODES) g_counts[t] = 0;
    if (t == 0) { g_xnorm = 0.0; g_ncand = 0; }
}

// ---------------------------------------------------------------------------
__device__ __forceinline__ float block_reduce_sum(float v) {
    __shared__ float red[32];
    int lane = threadIdx.x & 31;
    int w    = threadIdx.x >> 5;
    #pragma unroll
    for (int o = 16; o > 0; o >>= 1) v += __shfl_down_sync(0xffffffffu, v, o);
    if (lane == 0) red[w] = v;
    __syncthreads();
    if (w == 0) {
        v = (lane < ((int)blockDim.x >> 5)) ? red[lane] : 0.0f;
        #pragma unroll
        for (int o = 16; o > 0; o >>= 1) v += __shfl_down_sync(0xffffffffu, v, o);
    }
    return v;
}

// ---------------------------------------------------------------------------
// fp32 -> bf16 for inputs and codebook (8 floats/thread, 16B stores);
// accumulate sum(x^2) over inputs.
__global__ void k_convert(const float* __restrict__ A, const float* __restrict__ Cb) {
    const size_t nA8 = (size_t)B_ROWS * DIM / 8;
    const size_t nB8 = (size_t)E_CODES * DIM / 8;
    const size_t gid = blockIdx.x * (size_t)blockDim.x + threadIdx.x;
    const size_t stride = (size_t)gridDim.x * blockDim.x;
    float xs = 0.0f;
    for (size_t j = gid; j < nA8; j += stride) {
        const float4* pa = (const float4*)A + 2 * j;
        float4 v0 = pa[0], v1 = pa[1];
        uint4 hp;
        hp.x = pack_bf2(v0.x, v0.y); hp.y = pack_bf2(v0.z, v0.w);
        hp.z = pack_bf2(v1.x, v1.y); hp.w = pack_bf2(v1.z, v1.w);
        *(uint4*)(g_Ah + 8 * j) = hp;
        xs += v0.x * v0.x + v0.y * v0.y + v0.z * v0.z + v0.w * v0.w
            + v1.x * v1.x + v1.y * v1.y + v1.z * v1.z + v1.w * v1.w;
    }
    for (size_t j = gid; j < nB8; j += stride) {
        const float4* pb = (const float4*)Cb + 2 * j;
        float4 v0 = pb[0], v1 = pb[1];
        uint4 hp;
        hp.x = pack_bf2(v0.x, v0.y); hp.y = pack_bf2(v0.z, v0.w);
        hp.z = pack_bf2(v1.x, v1.y); hp.w = pack_bf2(v1.z, v1.w);
        *(uint4*)(g_Bh + 8 * j) = hp;
    }
    float tot = block_reduce_sum(xs);
    if (threadIdx.x == 0) atomicAdd(&g_xnorm, (double)tot);
}

// ---------------------------------------------------------------------------
// ||e||^2 per codebook row (fp32, from original codebook; deterministic tree)
__global__ void k_cbnorm(const float* __restrict__ cb) {
    int e = blockIdx.x;
    const float4* row = (const float4*)(cb + (size_t)e * DIM);
    float s = 0.0f;
    for (int j = threadIdx.x; j < DIM / 4; j += blockDim.x) {
        float4 v = row[j];
        s += v.x * v.x + v.y * v.y + v.z * v.z + v.w * v.w;
    }
    float tot = block_reduce_sum(s);
    if (threadIdx.x == 0) g_cb_norm[e] = tot;
}

// ---------------------------------------------------------------------------
// bf16 GEMM via mma.sync (HMMA): dot(x_b, e_n) fp32 accum, single product.
// CTA tile 128x128, 8 warps (warp tile 32x64), KC=64, 3-stage cp.async.
// Loader addressing hoisted: per thread, 2 running src pointers + constant
// dst offsets (32-row stride preserves swizzle bits, so dst is uniform-inc).
#define MT      128
#define NT      128
#define KC      64
#define NSTAGE  3
#define KSLICE  (DIM / KSPLIT)               // 4096
#define ITERS   (KSLICE / KC)                // 64
#define TILE_B  (128 * 128)                  // 16 KB
#define STAGE_B (2 * TILE_B)                 // 32 KB
#define SMEM_TOTAL (NSTAGE * STAGE_B)        // 98304 B

__global__ void __launch_bounds__(256, 2) k_mma() {
    extern __shared__ __align__(128) char smem[];
    const uint32_t sb = smem_u32(smem);
    const int tid  = threadIdx.x;
    const int wid  = tid >> 5;
    const int lane = tid & 31;
    const int wm   = wid & 3;                // m block (32 rows)
    const int wn   = wid >> 2;               // n block (64 cols)
    const int m0   = blockIdx.x * MT;
    const int n0   = blockIdx.y * NT;
    const int kz   = blockIdx.z * KSLICE;

    // loader thread geometry: row r0 = tid>>3 (0..31, +32*jj), chunk c = tid&7
    const int r0 = tid >> 3;
    const int c  = tid & 7;
    const __nv_bfloat16* srcA = g_Ah + (size_t)(m0 + r0) * DIM + kz + c * 8;
    const __nv_bfloat16* srcB = g_Bh + (size_t)(n0 + r0) * DIM + kz + c * 8;
    const uint32_t dst0 = sb + swz((uint32_t)(r0 * 128 + c * 16));

    float acc[2][8][4];
    #pragma unroll
    for (int mi = 0; mi < 2; mi++)
        #pragma unroll
        for (int nj = 0; nj < 8; nj++)
            #pragma unroll
            for (int q = 0; q < 4; q++) acc[mi][nj][q] = 0.0f;

    // prologue: stages 0,1
    #pragma unroll
    for (int p = 0; p < NSTAGE - 1; p++) {
        uint32_t d = dst0 + p * STAGE_B;
        #pragma unroll
        for (int jj = 0; jj < 4; jj++) {
            CP_ASYNC16(d + jj * 4096,          srcA + (size_t)jj * 32 * DIM);
            CP_ASYNC16(d + TILE_B + jj * 4096, srcB + (size_t)jj * 32 * DIM);
        }
        CP_COMMIT();
        srcA += KC; srcB += KC;
    }

    const uint32_t lrow = (lane & 15);
    const uint32_t lcol = (lane >> 4) * 16;

    int st_load = NSTAGE - 1;                 // stage to fill next
    for (int i = 0; i < ITERS; i++) {
        const int st = i % NSTAGE;
        CP_WAIT1();
        __syncthreads();
        if (i + NSTAGE - 1 < ITERS) {
            uint32_t d = dst0 + st_load * STAGE_B;
            #pragma unroll
            for (int jj = 0; jj < 4; jj++) {
                CP_ASYNC16(d + jj * 4096,          srcA + (size_t)jj * 32 * DIM);
                CP_ASYNC16(d + TILE_B + jj * 4096, srcB + (size_t)jj * 32 * DIM);
            }
            srcA += KC; srcB += KC;
            if (++st_load == NSTAGE) st_load = 0;
        }
        CP_COMMIT();

        const uint32_t s0 = sb + st * STAGE_B;
        #pragma unroll
        for (int ks = 0; ks < 4; ks++) {
            const uint32_t ko = ks * 32 + lcol;
            uint32_t a[2][4], b[4][4];
            #pragma unroll
            for (int mi = 0; mi < 2; mi++) {
                uint32_t ro = (wm * 32 + mi * 16 + lrow) * 128;
                LDSM_X4(a[mi], s0 + swz(ro + ko));
            }
            #pragma unroll
            for (int nq = 0; nq < 4; nq++) {
                uint32_t ro = (wn * 64 + nq * 16 + lrow) * 128;
                LDSM_X4(b[nq], s0 + TILE_B + swz(ro + ko));
            }
            #pragma unroll
            for (int nq = 0; nq < 4; nq++)
                #pragma unroll
                for (int mi = 0; mi < 2; mi++) {
                    MMA_BF16(acc[mi][2 * nq],     a[mi][0], a[mi][1], a[mi][2], a[mi][3],
                             b[nq][0], b[nq][2]);
                    MMA_BF16(acc[mi][2 * nq + 1], a[mi][0], a[mi][1], a[mi][2], a[mi][3],
                             b[nq][1], b[nq][3]);
                }
        }
    }

    // epilogue: write partial dots
    #pragma unroll
    for (int mi = 0; mi < 2; mi++) {
        #pragma unroll
        for (int nj = 0; nj < 8; nj++) {
            int row = m0 + wm * 32 + mi * 16 + (lane >> 2);
            int col = n0 + wn * 64 + nj * 8 + (lane & 3) * 2;
            float* d = &g_Dpart[((size_t)blockIdx.z * B_ROWS + row) * E_CODES + col];
            *(float2*)d = make_float2(acc[mi][nj][0], acc[mi][nj][1]);
            *(float2*)(d + 8 * E_CODES) = make_float2(acc[mi][nj][2], acc[mi][nj][3]);
        }
    }
}

// ---------------------------------------------------------------------------
// bf16 argmin per row + near-tie candidate extraction (one warp per row).
// float4 loads over Dpart; writes sentinel itself when refinement is needed.
__global__ void k_argmin() {
    const int row  = blockIdx.x * 8 + (threadIdx.x >> 5);
    const int lane = threadIdx.x & 31;
    const size_t SL = (size_t)B_ROWS * E_CODES;
    const float4* d4 = (const float4*)&g_Dpart[(size_t)row * E_CODES];
    float s[16];
    float m = 3.4e38f;
    #pragma unroll
    for (int j = 0; j < 4; j++) {
        int v4 = j * 32 + lane;                    // float4 index within row
        float4 dot = d4[v4];
        #pragma unroll
        for (int z = 1; z < KSPLIT; z++) {
            float4 t = d4[z * (SL / 4) + v4];
            dot.x += t.x; dot.y += t.y; dot.z += t.z; dot.w += t.w;
        }
        int e = v4 * 4;
        s[4 * j + 0] = g_cb_norm[e + 0] - 2.0f * dot.x;
        s[4 * j + 1] = g_cb_norm[e + 1] - 2.0f * dot.y;
        s[4 * j + 2] = g_cb_norm[e + 2] - 2.0f * dot.z;
        s[4 * j + 3] = g_cb_norm[e + 3] - 2.0f * dot.w;
        m = fminf(fminf(fminf(m, s[4 * j]), s[4 * j + 1]),
                  fminf(s[4 * j + 2], s[4 * j + 3]));
    }
    #pragma unroll
    for (int o = 16; o > 0; o >>= 1) m = fminf(m, __shfl_xor_sync(0xffffffffu, m, o));

    int cnt = 0;
    #pragma unroll
    for (int j = 0; j < 16; j++) cnt += (s[j] <= m + TH);
    #pragma unroll
    for (int o = 16; o > 0; o >>= 1) cnt += __shfl_xor_sync(0xffffffffu, cnt, o);

    if (cnt == 1) {
        int be = 0x7fffffff;
        #pragma unroll
        for (int j = 0; j < 16; j++)
            if (s[j] <= m + TH) be = (j >> 2) * 128 + lane * 4 + (j & 3);
        #pragma unroll
        for (int o = 16; o > 0; o >>= 1) be = min(be, __shfl_xor_sync(0xffffffffu, be, o));
        if (lane == 0)
            g_keys[row] = ((unsigned long long)f2sort(m) << 32) | (unsigned)be;
    } else {
        if (lane == 0) g_keys[row] = 0xFFFFFFFFFFFFFFFFULL;
        #pragma unroll
        for (int j = 0; j < 16; j++) {
            if (s[j] <= m + TH) {
                int e = (j >> 2) * 128 + lane * 4 + (j & 3);
                int slot = atomicAdd(&g_ncand, 1);
                if (slot < MAXCAND) g_cand[slot] = ((unsigned)row << 9) | (unsigned)e;
            }
        }
    }
}

// ---------------------------------------------------------------------------
// exact fp32 re-score of near-tie candidates; atomicMin sortable keys
__global__ void k_refine(const float* __restrict__ A, const float* __restrict__ Cb) {
    const int n = g_ncand;
    for (int j = blockIdx.x; j < n && j < MAXCAND; j += gridDim.x) {
        uint32_t cd  = g_cand[j];
        int row  = cd >> 9;
        int code = cd & 511;
        const float4* x = (const float4*)(A  + (size_t)row  * DIM);
        const float4* e = (const float4*)(Cb + (size_t)code * DIM);
        float dot = 0.0f;
        for (int i = threadIdx.x; i < DIM / 4; i += blockDim.x) {
            float4 xv = x[i], ev = e[i];
            dot += xv.x * ev.x + xv.y * ev.y + xv.z * ev.z + xv.w * ev.w;
        }
        float tot = block_reduce_sum(dot);
        if (threadIdx.x == 0) {
            float sc = g_cb_norm[code] - 2.0f * tot;
            unsigned long long key = ((unsigned long long)f2sort(sc) << 32) | (unsigned)code;
            atomicMin(&g_keys[row], key);
        }
        __syncthreads();
    }
}

// ---------------------------------------------------------------------------
// per row b: one-hot enc row + histogram + gather codebook row (vectorized).
__global__ void k_gather(const float* __restrict__ Cb, float* __restrict__ out) {
    int b   = blockIdx.x;
    int idx = (int)(g_keys[b] & 0xFFFFFFFFu);

    float2* enc = (float2*)(out + OFF_ENC + (size_t)b * E_CODES);
    if (threadIdx.x < 256) enc[threadIdx.x] = make_float2(0.f, 0.f);
    __syncthreads();
    if (threadIdx.x == 0) {
        out[OFF_ENC + (size_t)b * E_CODES + idx] = 1.0f;
        atomicAdd(&g_counts[idx], 1);
    }

    const float*  q  = Cb + (size_t)idx * DIM;
    const float4* q4 = (const float4*)q;
    float* o = out + OFF_Q + (size_t)b * DIM;
    if (threadIdx.x < 3) o[threadIdx.x] = q[threadIdx.x];        // prefix 0..2
    if (threadIdx.x == 3) o[DIM - 1] = q[DIM - 1];               // tail 16383
    float4* o4 = (float4*)(o + 3);                               // 16B aligned
    for (int t = threadIdx.x; t < (DIM - 4) / 4; t += blockDim.x) {
        float4 s0 = q4[t];
        float4 s1 = q4[t + 1];
        o4[t] = make_float4(s0.w, s1.x, s1.y, s1.z);
    }
}

// ---------------------------------------------------------------------------
// loss from Sum(best scores) + Sum(x^2); perplexity from counts
__global__ void k_finalize(float* __restrict__ out) {
    __shared__ double sh[512];
    int t = threadIdx.x;

    double s = 0.0;
    for (int r = t; r < B_ROWS; r += 512)
        s += (double)sort2f((unsigned)(g_keys[r] >> 32));
    sh[t] = s;
    __syncthreads();
    for (int k = 256; k > 0; k >>= 1) {
        if (t < k) sh[t] += sh[t + k];
        __syncthreads();
    }
    double score_sum = sh[0];
    __syncthreads();

    float p = (float)g_counts[t] / (float)B_ROWS;
    sh[t] = (double)(p * logf(p + 1e-10f));
    __syncthreads();
    for (int k = 256; k > 0; k >>= 1) {
        if (t < k) sh[t] += sh[t + k];
        __syncthreads();
    }
    if (t == 0) {
        out[OFF_PERP] = expf(-(float)sh[0]);
        double mse = (score_sum + g_xnorm) / ((double)B_ROWS * (double)DIM);
        out[OFF_LOSS] = (float)(1.25 * mse);
    }
}

// ---------------------------------------------------------------------------
extern "C" void kernel_launch(void* const* d_in, const int* in_sizes, int n_in,
                              void* d_out, int out_size) {
    const float* inputs   = (const float*)d_in[0];   // [2048, 16384]
    const float* codebook = (const float*)d_in[1];   // [512, 16384]
    float* out = (float*)d_out;
    (void)in_sizes; (void)n_in; (void)out_size;

    static int smem_set = 0;
    if (!smem_set) {
        cudaFuncSetAttribute(k_mma, cudaFuncAttributeMaxDynamicSharedMemorySize, SMEM_TOTAL);
        smem_set = 1;
    }

    k_init<<<2, 256>>>();
    k_convert<<<2048, 256>>>(inputs, codebook);
    k_cbnorm<<<E_CODES, 256>>>(codebook);

    dim3 grid(B_ROWS / MT, E_CODES / NT, KSPLIT);    // (16, 4, 4) = 256 CTAs
    k_mma<<<grid, 256, SMEM_TOTAL>>>();

    k_argmin<<<B_ROWS / 8, 256>>>();
    k_refine<<<1024, 256>>>(inputs, codebook);
    k_gather<<<B_ROWS, 256>>>(codebook, out);
    k_finalize<<<1, 512>>>(out);
}